// round 1
// baseline (speedup 1.0000x reference)
#include <cuda_runtime.h>

// Problem constants (fixed shapes per reference_code)
#define B_ROWS 4096
#define N_LEN  8192
#define M_FFT  4096           // complex FFT length (real-packed)
#define THREADS 512

#define MIN_IDX 273           // argmin |f - 40/60|  (f[i] = i*5/2048, exact fp32)
#define MAX_IDX 1707          // argmin |f - 250/60|
#define DF 0.00244140625f     // 10/4096, exact in fp32

__device__ float g_losses[B_ROWS];

// One CTA per row: pack real row into M_FFT complex points, iterative radix-2
// DIT FFT in shared memory, unpack to rfft bins [272..3415], compute SNR loss.
__global__ void __launch_bounds__(THREADS) snr_fft_kernel(
    const float* __restrict__ outputs,
    const float* __restrict__ targets)
{
    extern __shared__ float smem[];
    float2* z  = reinterpret_cast<float2*>(smem);              // M_FFT float2 = 32KB
    float2* tw = reinterpret_cast<float2*>(smem) + M_FFT;      // M_FFT/2 float2 = 16KB

    const int tid = threadIdx.x;
    const int row = blockIdx.x;

    // Twiddle table: tw[p] = exp(-2*pi*i * p / M_FFT), p in [0, 2048)
    for (int p = tid; p < M_FFT / 2; p += THREADS) {
        float s, c;
        sincospif(-(float)p * (1.0f / 2048.0f), &s, &c);   // angle = -pi*p/2048
        tw[p] = make_float2(c, s);
    }

    // Load row, pack pairs (x[2j], x[2j+1]) as complex, scatter bit-reversed.
    const float2* xrow = reinterpret_cast<const float2*>(outputs) + (size_t)row * M_FFT;
    for (int j = tid; j < M_FFT; j += THREADS) {
        float2 v = xrow[j];                 // coalesced 8B loads
        int br = __brev(j) >> 20;           // 12-bit reversal
        z[br] = v;
    }
    __syncthreads();

    // 12 radix-2 stages
    #pragma unroll 1
    for (int s = 1; s <= 12; ++s) {
        const int half = 1 << (s - 1);
        for (int b = tid; b < M_FFT / 2; b += THREADS) {
            int pos = b & (half - 1);
            int i0  = ((b >> (s - 1)) << s) + pos;
            int i1  = i0 + half;
            float2 w = tw[pos << (12 - s)];
            float2 a = z[i0];
            float2 c = z[i1];
            float tr = w.x * c.x - w.y * c.y;
            float ti = w.x * c.y + w.y * c.x;
            z[i1] = make_float2(a.x - tr, a.y - ti);
            z[i0] = make_float2(a.x + tr, a.y + ti);
        }
        __syncthreads();
    }

    // Per-row r = argmin_i |f[i] - target| (first-min tie rule, like jnp.argmin)
    const float tgt = targets[row];
    int base = (int)floorf(tgt / DF) - 1;
    if (base < 0) base = 0;
    if (base > M_FFT - 3) base = M_FFT - 3;
    int r = base;
    float best = fabsf((float)base * DF - tgt);
    #pragma unroll
    for (int i = 1; i <= 3; ++i) {
        float d = fabsf((float)(base + i) * DF - tgt);
        if (d < best) { best = d; r = base + i; }
    }
    const int r2 = 2 * r;

    // Unpack rfft bins and accumulate signal / noise energies.
    // Needed k range: [r-1 .. 2r+1] U [273,1707) is a subset of [272, 3415].
    float sig = 0.0f, noi = 0.0f;
    for (int k = 272 + tid; k <= 3415; k += THREADS) {
        float2 Z1 = z[k];
        float2 Z2 = z[M_FFT - k];
        float Er = 0.5f * (Z1.x + Z2.x);
        float Ei = 0.5f * (Z1.y - Z2.y);
        float Or = 0.5f * (Z1.y + Z2.y);
        float Oi = 0.5f * (Z2.x - Z1.x);
        float sn, c;
        sincospif(-(float)k * (1.0f / 4096.0f), &sn, &c);  // exp(-2*pi*i*k/8192)
        float Xr = Er + c * Or - sn * Oi;
        float Xi = Ei + c * Oi + sn * Or;
        float p = (Xr * Xr + Xi * Xi) * (1.0f / (float)N_LEN);  // |rfft/sqrt(n)|^2

        float u = (k == r || k == r2) ? 1.0f
                : ((k == r - 1 || k == r + 1) ? 0.5f : 0.0f);
        bool inr = (k >= MIN_IDX) && (k < MAX_IDX);
        float w = (!inr || k == r2 - 1 || k == r2 + 1) ? 0.0f : (1.0f - u);

        sig += p * u;
        noi += p * w;
    }

    // Reduce across 512 threads (reuse twiddle area as scratch; all tw reads done)
    #pragma unroll
    for (int o = 16; o > 0; o >>= 1) {
        sig += __shfl_down_sync(0xffffffffu, sig, o);
        noi += __shfl_down_sync(0xffffffffu, noi, o);
    }
    float* red = reinterpret_cast<float*>(tw);
    const int wid = tid >> 5, lane = tid & 31;
    __syncthreads();
    if (lane == 0) { red[wid] = sig; red[16 + wid] = noi; }
    __syncthreads();
    if (tid == 0) {
        float S = 0.0f, Nq = 0.0f;
        #pragma unroll
        for (int i = 0; i < 16; ++i) { S += red[i]; Nq += red[16 + i]; }
        g_losses[row] = -10.0f * log10f(S / (Nq + 1.0f));
    }
}

// Deterministic mean over the 4096 per-row losses.
__global__ void __launch_bounds__(512) mean_kernel(float* __restrict__ out)
{
    __shared__ float red[16];
    const int tid = threadIdx.x;
    float s = 0.0f;
    for (int i = tid; i < B_ROWS; i += 512) s += g_losses[i];
    #pragma unroll
    for (int o = 16; o > 0; o >>= 1) s += __shfl_down_sync(0xffffffffu, s, o);
    if ((tid & 31) == 0) red[tid >> 5] = s;
    __syncthreads();
    if (tid == 0) {
        float t = 0.0f;
        #pragma unroll
        for (int i = 0; i < 16; ++i) t += red[i];
        out[0] = t * (1.0f / (float)B_ROWS);
    }
}

extern "C" void kernel_launch(void* const* d_in, const int* in_sizes, int n_in,
                              void* d_out, int out_size)
{
    const float* outputs = (const float*)d_in[0];   // [4096, 8192] f32
    const float* targets = (const float*)d_in[1];   // [4096, 1] f32
    (void)in_sizes; (void)n_in; (void)out_size;

    const size_t shmem = sizeof(float2) * (M_FFT + M_FFT / 2);  // 49152 B
    // Idempotent, executes immediately (not a stream op) — safe under capture.
    cudaFuncSetAttribute(snr_fft_kernel,
                         cudaFuncAttributeMaxDynamicSharedMemorySize, 65536);

    snr_fft_kernel<<<B_ROWS, THREADS, shmem>>>(outputs, targets);
    mean_kernel<<<1, 512>>>((float*)d_out);
}

// round 2
// speedup vs baseline: 3.3261x; 3.3261x over previous
#include <cuda_runtime.h>

#define B_ROWS 4096
#define N_LEN  8192
#define M_FFT  4096
#define THREADS 512

#define MIN_IDX 273           // argmin |f - 40/60|  (f[i] = i*5/2048, exact fp32)
#define MAX_IDX 1707          // argmin |f - 250/60|
#define DF 0.00244140625f     // 10/4096, exact fp32

__device__ float g_losses[B_ROWS];
__device__ float g_twc[2048];   // cos(-2*pi*p/4096)
__device__ float g_tws[2048];   // sin(-2*pi*p/4096)

// Build the twiddle table ONCE per launch (was: per-CTA = 16.8M MUFU ops)
__global__ void twiddle_init_kernel()
{
    int p = blockIdx.x * blockDim.x + threadIdx.x;   // 2048 threads
    float s, c;
    sincospif(-(float)p * (1.0f / 2048.0f), &s, &c); // angle = -2*pi*p/4096
    g_twc[p] = c;
    g_tws[p] = s;
}

// XOR swizzle for shared-memory bank-conflict avoidance (SoA float arrays).
__device__ __forceinline__ int S(int i) { return i ^ ((i >> 6) & 31); }

__device__ __forceinline__ void cmul(float ar, float ai, float br, float bi,
                                     float& cr, float& ci)
{
    cr = ar * br - ai * bi;
    ci = ar * bi + ai * br;
}

// 8-point DFT, natural order in/out, in-place on register arrays.
__device__ __forceinline__ void dft8(float* xr, float* xi)
{
    const float C = 0.70710678118654752f;
    float t0r = xr[0] + xr[4], t0i = xi[0] + xi[4];
    float t1r = xr[0] - xr[4], t1i = xi[0] - xi[4];
    float t2r = xr[2] + xr[6], t2i = xi[2] + xi[6];
    float t3r = xr[2] - xr[6], t3i = xi[2] - xi[6];
    float E0r = t0r + t2r, E0i = t0i + t2i;
    float E2r = t0r - t2r, E2i = t0i - t2i;
    float E1r = t1r + t3i, E1i = t1i - t3r;    // t1 - i*t3
    float E3r = t1r - t3i, E3i = t1i + t3r;    // t1 + i*t3
    float s0r = xr[1] + xr[5], s0i = xi[1] + xi[5];
    float s1r = xr[1] - xr[5], s1i = xi[1] - xi[5];
    float s2r = xr[3] + xr[7], s2i = xi[3] + xi[7];
    float s3r = xr[3] - xr[7], s3i = xi[3] - xi[7];
    float O0r = s0r + s2r, O0i = s0i + s2i;
    float O2r = s0r - s2r, O2i = s0i - s2i;
    float O1r = s1r + s3i, O1i = s1i - s3r;
    float O3r = s1r - s3i, O3i = s1i + s3r;
    // P_j = w8^j * O_j
    float P1r = C * (O1r + O1i), P1i = C * (O1i - O1r);
    float P2r = O2i,             P2i = -O2r;
    float P3r = C * (O3i - O3r), P3i = -C * (O3r + O3i);
    xr[0] = E0r + O0r; xi[0] = E0i + O0i;
    xr[4] = E0r - O0r; xi[4] = E0i - O0i;
    xr[1] = E1r + P1r; xi[1] = E1i + P1i;
    xr[5] = E1r - P1r; xi[5] = E1i - P1i;
    xr[2] = E2r + P2r; xi[2] = E2i + P2i;
    xr[6] = E2r - P2r; xi[6] = E2i - P2i;
    xr[3] = E3r + P3r; xi[3] = E3i + P3i;
    xr[7] = E3r - P3r; xi[7] = E3i - P3i;
}

// One radix-8 DIT stage (L = span = ns/8). Lane mappings chosen so shared
// accesses are (near) conflict-free under the S() swizzle.
template <int L>
__device__ __forceinline__ void stage(float* zr, float* zi,
                                      const float* tc, const float* ts, int tid)
{
    int p, g;
    if (L == 8)       { p = tid >> 6; g = tid & 63; }  // group-major in lanes
    else if (L == 64) { p = tid >> 3; g = tid & 7;  }
    else              { p = tid;      g = 0;        }  // L == 512
    const int base = g * (8 * L) + p;
    const int tix  = p * (512 / L);      // < 512 always
    const float w1r = tc[tix], w1i = ts[tix];

    float xr[8], xi[8];
    {
        int q = S(base);
        xr[0] = zr[q]; xi[0] = zi[q];
    }
    float wr = w1r, wi = w1i;
    #pragma unroll
    for (int k = 1; k < 8; ++k) {
        int q = S(base + k * L);
        float ar = zr[q], ai = zi[q];
        cmul(ar, ai, wr, wi, xr[k], xi[k]);
        if (k < 7) { float nr, ni; cmul(wr, wi, w1r, w1i, nr, ni); wr = nr; wi = ni; }
    }
    dft8(xr, xi);
    #pragma unroll
    for (int k = 0; k < 8; ++k) {
        int q = S(base + k * L);
        zr[q] = xr[k]; zi[q] = xi[k];
    }
}

__global__ void __launch_bounds__(THREADS, 2) snr_fft_kernel(
    const float* __restrict__ outputs,
    const float* __restrict__ targets)
{
    extern __shared__ float smem[];
    float* zr = smem;                 // 4096 floats
    float* zi = smem + 4096;          // 4096 floats
    float* tc = smem + 8192;          // 2048 floats
    float* ts = smem + 10240;         // 2048 floats

    const int tid = threadIdx.x;
    const int row = blockIdx.x;

    // Copy twiddle table from gmem (L2-resident, same 16KB for all CTAs).
    #pragma unroll
    for (int p = tid; p < 2048; p += THREADS) { tc[p] = g_twc[p]; ts[p] = g_tws[p]; }

    // Coalesced load; scatter to base-8 digit-reversed, swizzled positions.
    const float2* xrow = reinterpret_cast<const float2*>(outputs) + (size_t)row * M_FFT;
    #pragma unroll
    for (int j = tid; j < M_FFT; j += THREADS) {
        float2 v = xrow[j];
        int dr = ((j & 7) << 9) | (((j >> 3) & 7) << 6) | (((j >> 6) & 7) << 3) | (j >> 9);
        int q = S(dr);
        zr[q] = v.x; zi[q] = v.y;
    }
    __syncthreads();

    // Stage 1 (ns=8): all twiddles are 1.
    {
        const int base = tid << 3;
        float xr[8], xi[8];
        #pragma unroll
        for (int k = 0; k < 8; ++k) { int q = S(base + k); xr[k] = zr[q]; xi[k] = zi[q]; }
        dft8(xr, xi);
        #pragma unroll
        for (int k = 0; k < 8; ++k) { int q = S(base + k); zr[q] = xr[k]; zi[q] = xi[k]; }
    }
    __syncthreads();
    stage<8>(zr, zi, tc, ts, tid);
    __syncthreads();
    stage<64>(zr, zi, tc, ts, tid);
    __syncthreads();
    stage<512>(zr, zi, tc, ts, tid);
    __syncthreads();

    // r = argmin_i |f[i] - target| (first-min tie rule)
    const float tgt = targets[row];
    int base = (int)floorf(tgt / DF) - 1;
    if (base < 0) base = 0;
    if (base > M_FFT - 3) base = M_FFT - 3;
    int r = base;
    float best = fabsf((float)base * DF - tgt);
    #pragma unroll
    for (int i = 1; i <= 3; ++i) {
        float d = fabsf((float)(base + i) * DF - tgt);
        if (d < best) { best = d; r = base + i; }
    }
    const int r2 = 2 * r;

    // exp(-i*pi/4096) for odd-k unpack twiddles
    const float Cr = 0.99999970586288222f;
    const float Ci = -0.00076699031874270449f;

    float sig = 0.0f, noi = 0.0f;
    for (int k = 272 + tid; k <= 3415; k += THREADS) {
        int q1 = S(k), q2 = S(M_FFT - k);
        float Z1r = zr[q1], Z1i = zi[q1];
        float Z2r = zr[q2], Z2i = zi[q2];
        float Er = 0.5f * (Z1r + Z2r);
        float Ei = 0.5f * (Z1i - Z2i);
        float Or = 0.5f * (Z1i + Z2i);
        float Oi = 0.5f * (Z2r - Z1r);
        // W = exp(-2*pi*i*k/8192): even k -> table[k/2]; odd k -> table[k/2]*C
        int m = k >> 1;
        float Wr = tc[m], Wi = ts[m];
        if (k & 1) { float nr, ni; cmul(Wr, Wi, Cr, Ci, nr, ni); Wr = nr; Wi = ni; }
        float Xr = Er + Wr * Or - Wi * Oi;
        float Xi = Ei + Wr * Oi + Wi * Or;
        float pwr = (Xr * Xr + Xi * Xi) * (1.0f / (float)N_LEN);

        float u = (k == r || k == r2) ? 1.0f
                : ((k == r - 1 || k == r + 1) ? 0.5f : 0.0f);
        bool inr = (k >= MIN_IDX) && (k < MAX_IDX);
        float w = (!inr || k == r2 - 1 || k == r2 + 1) ? 0.0f : (1.0f - u);

        sig += pwr * u;
        noi += pwr * w;
    }

    #pragma unroll
    for (int o = 16; o > 0; o >>= 1) {
        sig += __shfl_down_sync(0xffffffffu, sig, o);
        noi += __shfl_down_sync(0xffffffffu, noi, o);
    }
    const int wid = tid >> 5, lane = tid & 31;
    __syncthreads();                       // all smem reads done; reuse tc
    if (lane == 0) { tc[wid] = sig; tc[16 + wid] = noi; }
    __syncthreads();
    if (tid == 0) {
        float Sg = 0.0f, Nq = 0.0f;
        #pragma unroll
        for (int i = 0; i < 16; ++i) { Sg += tc[i]; Nq += tc[16 + i]; }
        g_losses[row] = -10.0f * log10f(Sg / (Nq + 1.0f));
    }
}

__global__ void __launch_bounds__(512) mean_kernel(float* __restrict__ out)
{
    __shared__ float red[16];
    const int tid = threadIdx.x;
    float s = 0.0f;
    for (int i = tid; i < B_ROWS; i += 512) s += g_losses[i];
    #pragma unroll
    for (int o = 16; o > 0; o >>= 1) s += __shfl_down_sync(0xffffffffu, s, o);
    if ((tid & 31) == 0) red[tid >> 5] = s;
    __syncthreads();
    if (tid == 0) {
        float t = 0.0f;
        #pragma unroll
        for (int i = 0; i < 16; ++i) t += red[i];
        out[0] = t * (1.0f / (float)B_ROWS);
    }
}

extern "C" void kernel_launch(void* const* d_in, const int* in_sizes, int n_in,
                              void* d_out, int out_size)
{
    const float* outputs = (const float*)d_in[0];   // [4096, 8192] f32
    const float* targets = (const float*)d_in[1];   // [4096, 1]    f32
    (void)in_sizes; (void)n_in; (void)out_size;

    const size_t shmem = sizeof(float) * (4096 * 2 + 2048 * 2);  // 49152 B
    cudaFuncSetAttribute(snr_fft_kernel,
                         cudaFuncAttributeMaxDynamicSharedMemorySize, 65536);

    twiddle_init_kernel<<<4, 512>>>();
    snr_fft_kernel<<<B_ROWS, THREADS, shmem>>>(outputs, targets);
    mean_kernel<<<1, 512>>>((float*)d_out);
}

// round 3
// speedup vs baseline: 3.8508x; 1.1577x over previous
#include <cuda_runtime.h>

#define B_ROWS 4096
#define N_LEN  8192
#define M_FFT  4096
#define THREADS 512

#define MIN_IDX 273           // argmin |f - 40/60|  (f[i] = i*5/2048, exact fp32)
#define MAX_IDX 1707          // argmin |f - 250/60|
#define DF 0.00244140625f     // 10/4096, exact fp32

__device__ float g_losses[B_ROWS];
__device__ __align__(16) float g_twc[2048];   // cos(-2*pi*p/4096)
__device__ __align__(16) float g_tws[2048];   // sin(-2*pi*p/4096)

// Build the twiddle table once per launch.
__global__ void twiddle_init_kernel()
{
    int p = blockIdx.x * blockDim.x + threadIdx.x;   // 2048 threads
    float s, c;
    sincospif(-(float)p * (1.0f / 2048.0f), &s, &c); // angle = -2*pi*p/4096
    g_twc[p] = c;
    g_tws[p] = s;
}

// Swizzle: conflict-free for the stage-1 write pattern and all three
// radix-8 stage read/write patterns below (verified per-lane).
__device__ __forceinline__ int S(int i)
{
    return i ^ ((i >> 6) & 31) ^ ((i >> 9) & 7);
}

__device__ __forceinline__ void cmul(float ar, float ai, float br, float bi,
                                     float& cr, float& ci)
{
    cr = ar * br - ai * bi;
    ci = ar * bi + ai * br;
}

// 8-point DFT (DIT), natural order, in-place on register arrays.
__device__ __forceinline__ void dft8(float* xr, float* xi)
{
    const float C = 0.70710678118654752f;
    float t0r = xr[0] + xr[4], t0i = xi[0] + xi[4];
    float t1r = xr[0] - xr[4], t1i = xi[0] - xi[4];
    float t2r = xr[2] + xr[6], t2i = xi[2] + xi[6];
    float t3r = xr[2] - xr[6], t3i = xi[2] - xi[6];
    float E0r = t0r + t2r, E0i = t0i + t2i;
    float E2r = t0r - t2r, E2i = t0i - t2i;
    float E1r = t1r + t3i, E1i = t1i - t3r;    // t1 - i*t3
    float E3r = t1r - t3i, E3i = t1i + t3r;    // t1 + i*t3
    float s0r = xr[1] + xr[5], s0i = xi[1] + xi[5];
    float s1r = xr[1] - xr[5], s1i = xi[1] - xi[5];
    float s2r = xr[3] + xr[7], s2i = xi[3] + xi[7];
    float s3r = xr[3] - xr[7], s3i = xi[3] - xi[7];
    float O0r = s0r + s2r, O0i = s0i + s2i;
    float O2r = s0r - s2r, O2i = s0i - s2i;
    float O1r = s1r + s3i, O1i = s1i - s3r;
    float O3r = s1r - s3i, O3i = s1i + s3r;
    float P1r = C * (O1r + O1i), P1i = C * (O1i - O1r);
    float P2r = O2i,             P2i = -O2r;
    float P3r = C * (O3i - O3r), P3i = -C * (O3r + O3i);
    xr[0] = E0r + O0r; xi[0] = E0i + O0i;
    xr[4] = E0r - O0r; xi[4] = E0i - O0i;
    xr[1] = E1r + P1r; xi[1] = E1i + P1i;
    xr[5] = E1r - P1r; xi[5] = E1i - P1i;
    xr[2] = E2r + P2r; xi[2] = E2i + P2i;
    xr[6] = E2r - P2r; xi[6] = E2i - P2i;
    xr[3] = E3r + P3r; xi[3] = E3i + P3i;
    xr[7] = E3r - P3r; xi[7] = E3i - P3i;
}

// One radix-8 DIT stage (L = span).
template <int L>
__device__ __forceinline__ void stage(float* zr, float* zi,
                                      const float* tc, const float* ts, int tid)
{
    int p, g;
    if (L == 8)       { p = tid >> 6; g = tid & 63; }
    else if (L == 64) { p = tid >> 3; g = tid & 7;  }
    else              { p = tid;      g = 0;        }  // L == 512
    const int base = g * (8 * L) + p;
    const int tix  = p * (512 / L);
    const float w1r = tc[tix], w1i = ts[tix];

    float xr[8], xi[8];
    {
        int q = S(base);
        xr[0] = zr[q]; xi[0] = zi[q];
    }
    float wr = w1r, wi = w1i;
    #pragma unroll
    for (int k = 1; k < 8; ++k) {
        int q = S(base + k * L);
        float ar = zr[q], ai = zi[q];
        cmul(ar, ai, wr, wi, xr[k], xi[k]);
        if (k < 7) { float nr, ni; cmul(wr, wi, w1r, w1i, nr, ni); wr = nr; wi = ni; }
    }
    dft8(xr, xi);
    #pragma unroll
    for (int k = 0; k < 8; ++k) {
        int q = S(base + k * L);
        zr[q] = xr[k]; zi[q] = xi[k];
    }
}

__global__ void __launch_bounds__(THREADS, 2) snr_fft_kernel(
    const float* __restrict__ outputs,
    const float* __restrict__ targets)
{
    extern __shared__ float smem[];
    float* zr = smem;                 // 4096 floats
    float* zi = smem + 4096;          // 4096 floats
    float* tc = smem + 8192;          // 2048 floats
    float* ts = smem + 10240;         // 2048 floats

    const int tid = threadIdx.x;
    const int row = blockIdx.x;

    // Vectorized twiddle copy from gmem (L2-resident, shared by all CTAs).
    {
        const float4* c4 = reinterpret_cast<const float4*>(g_twc);
        const float4* s4 = reinterpret_cast<const float4*>(g_tws);
        reinterpret_cast<float4*>(tc)[tid] = c4[tid];
        reinterpret_cast<float4*>(ts)[tid] = s4[tid];
    }

    // Fused coalesced load + stage 1 (twiddle-free dft8 in registers):
    // thread tid loads j = tid + 512k (k=0..7) — exactly the 8 inputs of one
    // stage-1 butterfly; results land at digit-reversed group t8 in smem.
    const float2* xrow = reinterpret_cast<const float2*>(outputs) + (size_t)row * M_FFT;
    {
        float xr[8], xi[8];
        #pragma unroll
        for (int k = 0; k < 8; ++k) {
            float2 v = xrow[tid + (k << 9)];
            xr[k] = v.x; xi[k] = v.y;
        }
        dft8(xr, xi);
        const int t8 = ((tid & 7) << 6) | (((tid >> 3) & 7) << 3) | (tid >> 6);
        #pragma unroll
        for (int k = 0; k < 8; ++k) {
            int q = S((t8 << 3) + k);
            zr[q] = xr[k]; zi[q] = xi[k];
        }
    }
    __syncthreads();

    stage<8>(zr, zi, tc, ts, tid);
    __syncthreads();
    stage<64>(zr, zi, tc, ts, tid);
    __syncthreads();
    stage<512>(zr, zi, tc, ts, tid);
    __syncthreads();

    // r = argmin_i |f[i] - target| (first-min tie rule)
    const float tgt = targets[row];
    int base = (int)floorf(tgt / DF) - 1;
    if (base < 0) base = 0;
    if (base > M_FFT - 3) base = M_FFT - 3;
    int r = base;
    float best = fabsf((float)base * DF - tgt);
    #pragma unroll
    for (int i = 1; i <= 3; ++i) {
        float d = fabsf((float)(base + i) * DF - tgt);
        if (d < best) { best = d; r = base + i; }
    }
    const int r2 = 2 * r;

    // exp(-i*pi/4096) for odd-k unpack twiddles
    const float Cr = 0.99999970586288222f;
    const float Ci = -0.00076699031874270449f;

    float sig = 0.0f, noi = 0.0f;
    for (int k = 272 + tid; k <= 3415; k += THREADS) {
        int q1 = S(k), q2 = S(M_FFT - k);
        float Z1r = zr[q1], Z1i = zi[q1];
        float Z2r = zr[q2], Z2i = zi[q2];
        float Er = 0.5f * (Z1r + Z2r);
        float Ei = 0.5f * (Z1i - Z2i);
        float Or = 0.5f * (Z1i + Z2i);
        float Oi = 0.5f * (Z2r - Z1r);
        int m = k >> 1;
        float Wr = tc[m], Wi = ts[m];
        if (k & 1) { float nr, ni; cmul(Wr, Wi, Cr, Ci, nr, ni); Wr = nr; Wi = ni; }
        float Xr = Er + Wr * Or - Wi * Oi;
        float Xi = Ei + Wr * Oi + Wi * Or;
        float pwr = (Xr * Xr + Xi * Xi) * (1.0f / (float)N_LEN);

        float u = (k == r || k == r2) ? 1.0f
                : ((k == r - 1 || k == r + 1) ? 0.5f : 0.0f);
        bool inr = (k >= MIN_IDX) && (k < MAX_IDX);
        float w = (!inr || k == r2 - 1 || k == r2 + 1) ? 0.0f : (1.0f - u);

        sig += pwr * u;
        noi += pwr * w;
    }

    #pragma unroll
    for (int o = 16; o > 0; o >>= 1) {
        sig += __shfl_down_sync(0xffffffffu, sig, o);
        noi += __shfl_down_sync(0xffffffffu, noi, o);
    }
    const int wid = tid >> 5, lane = tid & 31;
    __syncthreads();                       // smem reads done; reuse tc
    if (lane == 0) { tc[wid] = sig; tc[16 + wid] = noi; }
    __syncthreads();
    if (tid == 0) {
        float Sg = 0.0f, Nq = 0.0f;
        #pragma unroll
        for (int i = 0; i < 16; ++i) { Sg += tc[i]; Nq += tc[16 + i]; }
        g_losses[row] = -10.0f * log10f(Sg / (Nq + 1.0f));
    }
}

__global__ void __launch_bounds__(512) mean_kernel(float* __restrict__ out)
{
    __shared__ float red[16];
    const int tid = threadIdx.x;
    float s = 0.0f;
    for (int i = tid; i < B_ROWS; i += 512) s += g_losses[i];
    #pragma unroll
    for (int o = 16; o > 0; o >>= 1) s += __shfl_down_sync(0xffffffffu, s, o);
    if ((tid & 31) == 0) red[tid >> 5] = s;
    __syncthreads();
    if (tid == 0) {
        float t = 0.0f;
        #pragma unroll
        for (int i = 0; i < 16; ++i) t += red[i];
        out[0] = t * (1.0f / (float)B_ROWS);
    }
}

extern "C" void kernel_launch(void* const* d_in, const int* in_sizes, int n_in,
                              void* d_out, int out_size)
{
    const float* outputs = (const float*)d_in[0];   // [4096, 8192] f32
    const float* targets = (const float*)d_in[1];   // [4096, 1]    f32
    (void)in_sizes; (void)n_in; (void)out_size;

    const size_t shmem = sizeof(float) * (4096 * 2 + 2048 * 2);  // 49152 B
    cudaFuncSetAttribute(snr_fft_kernel,
                         cudaFuncAttributeMaxDynamicSharedMemorySize, 65536);

    twiddle_init_kernel<<<4, 512>>>();
    snr_fft_kernel<<<B_ROWS, THREADS, shmem>>>(outputs, targets);
    mean_kernel<<<1, 512>>>((float*)d_out);
}

// round 4
// speedup vs baseline: 4.3244x; 1.1230x over previous
#include <cuda_runtime.h>

#define B_ROWS 4096
#define N_LEN  8192
#define M_FFT  4096
#define THREADS 512

#define MIN_IDX 273           // argmin |f - 40/60|  (f[i] = i*5/2048, exact fp32)
#define MAX_IDX 1707          // argmin |f - 250/60|
#define DF 0.00244140625f     // 10/4096, exact fp32

__device__ float g_losses[B_ROWS];
__device__ __align__(16) float g_twc[2048];   // cos(-2*pi*p/4096)
__device__ __align__(16) float g_tws[2048];   // sin(-2*pi*p/4096)
__device__ unsigned int g_ctr = 0;            // last-CTA-done counter (self-resetting)

// Build the twiddle table once per launch.
__global__ void twiddle_init_kernel()
{
    int p = blockIdx.x * blockDim.x + threadIdx.x;   // 2048 threads
    float s, c;
    sincospif(-(float)p * (1.0f / 2048.0f), &s, &c); // angle = -2*pi*p/4096
    g_twc[p] = c;
    g_tws[p] = s;
}

// Swizzle: conflict-free for all stage patterns (verified R2/R3, rel_err 0).
// GF(2)-linear: S(a ^ b) = S(a) ^ S(b).
__device__ __forceinline__ int S(int i)
{
    return i ^ ((i >> 6) & 31) ^ ((i >> 9) & 7);
}

__device__ __forceinline__ void cmul(float ar, float ai, float br, float bi,
                                     float& cr, float& ci)
{
    cr = ar * br - ai * bi;
    ci = ar * bi + ai * br;
}

// 8-point DFT (DIT), natural order, in-place on register arrays.
__device__ __forceinline__ void dft8(float* xr, float* xi)
{
    const float C = 0.70710678118654752f;
    float t0r = xr[0] + xr[4], t0i = xi[0] + xi[4];
    float t1r = xr[0] - xr[4], t1i = xi[0] - xi[4];
    float t2r = xr[2] + xr[6], t2i = xi[2] + xi[6];
    float t3r = xr[2] - xr[6], t3i = xi[2] - xi[6];
    float E0r = t0r + t2r, E0i = t0i + t2i;
    float E2r = t0r - t2r, E2i = t0i - t2i;
    float E1r = t1r + t3i, E1i = t1i - t3r;    // t1 - i*t3
    float E3r = t1r - t3i, E3i = t1i + t3r;    // t1 + i*t3
    float s0r = xr[1] + xr[5], s0i = xi[1] + xi[5];
    float s1r = xr[1] - xr[5], s1i = xi[1] - xi[5];
    float s2r = xr[3] + xr[7], s2i = xi[3] + xi[7];
    float s3r = xr[3] - xr[7], s3i = xi[3] - xi[7];
    float O0r = s0r + s2r, O0i = s0i + s2i;
    float O2r = s0r - s2r, O2i = s0i - s2i;
    float O1r = s1r + s3i, O1i = s1i - s3r;
    float O3r = s1r - s3i, O3i = s1i + s3r;
    float P1r = C * (O1r + O1i), P1i = C * (O1i - O1r);
    float P2r = O2i,             P2i = -O2r;
    float P3r = C * (O3i - O3r), P3i = -C * (O3r + O3i);
    xr[0] = E0r + O0r; xi[0] = E0i + O0i;
    xr[4] = E0r - O0r; xi[4] = E0i - O0i;
    xr[1] = E1r + P1r; xi[1] = E1i + P1i;
    xr[5] = E1r - P1r; xi[5] = E1i - P1i;
    xr[2] = E2r + P2r; xi[2] = E2i + P2i;
    xr[6] = E2r - P2r; xi[6] = E2i - P2i;
    xr[3] = E3r + P3r; xi[3] = E3i + P3i;
    xr[7] = E3r - P3r; xi[7] = E3i - P3i;
}

// One radix-8 DIT stage. Addresses: q_k = S(base) ^ S(k*L), with S(k*L)
// compile-time (digit bits of base at [log2 L, log2 L + 3) are zero).
template <int L>
__device__ __forceinline__ void stage(float* zr, float* zi,
                                      const float* tc, const float* ts, int tid)
{
    int p, g;
    if (L == 8)       { p = tid >> 6; g = tid & 63; }
    else if (L == 64) { p = tid >> 3; g = tid & 7;  }
    else              { p = tid;      g = 0;        }  // L == 512
    const int base = g * (8 * L) + p;
    const int q0   = S(base);
    const int tix  = p * (512 / L);
    const float w1r = tc[tix], w1i = ts[tix];

    float xr[8], xi[8];
    xr[0] = zr[q0]; xi[0] = zi[q0];
    float wr = w1r, wi = w1i;
    #pragma unroll
    for (int k = 1; k < 8; ++k) {
        const int C_k = (k * L) ^ (((k * L) >> 6) & 31) ^ (((k * L) >> 9) & 7); // S(k*L), constexpr
        int q = q0 ^ C_k;
        float ar = zr[q], ai = zi[q];
        cmul(ar, ai, wr, wi, xr[k], xi[k]);
        if (k < 7) { float nr, ni; cmul(wr, wi, w1r, w1i, nr, ni); wr = nr; wi = ni; }
    }
    dft8(xr, xi);
    #pragma unroll
    for (int k = 0; k < 8; ++k) {
        const int C_k = (k * L) ^ (((k * L) >> 6) & 31) ^ (((k * L) >> 9) & 7);
        int q = q0 ^ C_k;
        zr[q] = xr[k]; zi[q] = xi[k];
    }
}

__global__ void __launch_bounds__(THREADS, 2) snr_fft_kernel(
    const float* __restrict__ outputs,
    const float* __restrict__ targets,
    float* __restrict__ d_out)
{
    extern __shared__ float smem[];
    float* zr = smem;                 // 4096 floats
    float* zi = smem + 4096;          // 4096 floats
    float* tc = smem + 8192;          // 2048 floats
    float* ts = smem + 10240;         // 2048 floats

    const int tid = threadIdx.x;
    const int row = blockIdx.x;

    // Vectorized twiddle copy from gmem (L2-resident, shared by all CTAs).
    {
        const float4* c4 = reinterpret_cast<const float4*>(g_twc);
        const float4* s4 = reinterpret_cast<const float4*>(g_tws);
        reinterpret_cast<float4*>(tc)[tid] = c4[tid];
        reinterpret_cast<float4*>(ts)[tid] = s4[tid];
    }

    // Fused coalesced load + stage 1 (twiddle-free dft8 in registers).
    const float2* xrow = reinterpret_cast<const float2*>(outputs) + (size_t)row * M_FFT;
    {
        float xr[8], xi[8];
        #pragma unroll
        for (int k = 0; k < 8; ++k) {
            float2 v = xrow[tid + (k << 9)];
            xr[k] = v.x; xi[k] = v.y;
        }
        dft8(xr, xi);
        const int t8 = ((tid & 7) << 6) | (((tid >> 3) & 7) << 3) | (tid >> 6);
        const int q0 = S(t8 << 3);
        #pragma unroll
        for (int k = 0; k < 8; ++k) {   // S(k) = k for k < 8
            int q = q0 ^ k;
            zr[q] = xr[k]; zi[q] = xi[k];
        }
    }
    __syncthreads();

    stage<8>(zr, zi, tc, ts, tid);
    __syncthreads();
    stage<64>(zr, zi, tc, ts, tid);
    __syncthreads();
    stage<512>(zr, zi, tc, ts, tid);
    __syncthreads();

    // r = argmin_i |f[i] - target| (first-min tie rule)
    const float tgt = targets[row];
    int base = (int)floorf(tgt / DF) - 1;
    if (base < 0) base = 0;
    if (base > M_FFT - 3) base = M_FFT - 3;
    int r = base;
    float best = fabsf((float)base * DF - tgt);
    #pragma unroll
    for (int i = 1; i <= 3; ++i) {
        float d = fabsf((float)(base + i) * DF - tgt);
        if (d < best) { best = d; r = base + i; }
    }
    const int r2 = 2 * r;

    // exp(-i*pi/4096) for odd-k unpack twiddles
    const float Cr = 0.99999970586288222f;
    const float Ci = -0.00076699031874270449f;

    // Paired epilogue: k in [272, 2048]; bins b=k and b=4096-k share
    // (Z[k], Z[4096-k]); W[4096-k] = -conj(W[k]).
    float sig = 0.0f, noi = 0.0f;
    for (int k = 272 + tid; k <= 2048; k += THREADS) {
        int q1 = S(k), q2 = S(M_FFT - k);
        float Z1r = zr[q1], Z1i = zi[q1];
        float Z2r = zr[q2], Z2i = zi[q2];
        float Er = 0.5f * (Z1r + Z2r);
        float Ei = 0.5f * (Z1i - Z2i);
        float Or = 0.5f * (Z1i + Z2i);
        float Oi = 0.5f * (Z2r - Z1r);
        int mm = k >> 1;
        float Wr = tc[mm], Wi = ts[mm];
        if (k & 1) { float nr, ni; cmul(Wr, Wi, Cr, Ci, nr, ni); Wr = nr; Wi = ni; }

        // Bin k
        {
            float Xr = Er + Wr * Or - Wi * Oi;
            float Xi = Ei + Wr * Oi + Wi * Or;
            float pwr = (Xr * Xr + Xi * Xi) * (1.0f / (float)N_LEN);
            float u = (k == r || k == r2) ? 1.0f
                    : ((k == r - 1 || k == r + 1) ? 0.5f : 0.0f);
            bool inr = (k >= MIN_IDX) && (k < MAX_IDX);
            float w = (!inr || k == r2 - 1 || k == r2 + 1) ? 0.0f : (1.0f - u);
            sig += pwr * u;
            noi += pwr * w;
        }

        // Bin m = 4096 - k (only for k < 2048; m <= 3415 requires k >= 681).
        int m = M_FFT - k;
        if (k >= 681 && k < 2048) {
            // E(m) = (Er, -Ei); O(m) = (Or, -Oi); W(m) = (-Wr, Wi)
            float Xr = Er - Wr * Or - Wi * Oi;
            float Xi = -Ei - Wr * Oi + Wi * Or;
            float pwr = (Xr * Xr + Xi * Xi) * (1.0f / (float)N_LEN);
            float u = (m == r || m == r2) ? 1.0f
                    : ((m == r - 1 || m == r + 1) ? 0.5f : 0.0f);
            // m >= 2049 > MAX_IDX always -> in-range false -> w = 0
            sig += pwr * u;
            // noi += 0
        }
    }

    #pragma unroll
    for (int o = 16; o > 0; o >>= 1) {
        sig += __shfl_down_sync(0xffffffffu, sig, o);
        noi += __shfl_down_sync(0xffffffffu, noi, o);
    }
    const int wid = tid >> 5, lane = tid & 31;
    __syncthreads();                       // smem reads done; reuse tc
    if (lane == 0) { tc[wid] = sig; tc[16 + wid] = noi; }
    __syncthreads();

    __shared__ bool is_last;
    if (tid == 0) {
        float Sg = 0.0f, Nq = 0.0f;
        #pragma unroll
        for (int i = 0; i < 16; ++i) { Sg += tc[i]; Nq += tc[16 + i]; }
        g_losses[row] = -10.0f * log10f(Sg / (Nq + 1.0f));
        __threadfence();                               // publish g_losses[row]
        unsigned int old = atomicAdd(&g_ctr, 1u);
        is_last = (old == (unsigned int)(B_ROWS - 1));
    }
    __syncthreads();

    // Last CTA computes the mean (fixed-order, deterministic) and resets ctr.
    if (is_last) {
        float s = 0.0f;
        for (int i = tid; i < B_ROWS; i += THREADS) s += g_losses[i];
        #pragma unroll
        for (int o = 16; o > 0; o >>= 1) s += __shfl_down_sync(0xffffffffu, s, o);
        __syncthreads();
        if (lane == 0) tc[wid] = s;
        __syncthreads();
        if (tid == 0) {
            float t = 0.0f;
            #pragma unroll
            for (int i = 0; i < 16; ++i) t += tc[i];
            d_out[0] = t * (1.0f / (float)B_ROWS);
            g_ctr = 0;                                 // reset for next replay
        }
    }
}

extern "C" void kernel_launch(void* const* d_in, const int* in_sizes, int n_in,
                              void* d_out, int out_size)
{
    const float* outputs = (const float*)d_in[0];   // [4096, 8192] f32
    const float* targets = (const float*)d_in[1];   // [4096, 1]    f32
    (void)in_sizes; (void)n_in; (void)out_size;

    const size_t shmem = sizeof(float) * (4096 * 2 + 2048 * 2);  // 49152 B
    cudaFuncSetAttribute(snr_fft_kernel,
                         cudaFuncAttributeMaxDynamicSharedMemorySize, 65536);

    twiddle_init_kernel<<<4, 512>>>();
    snr_fft_kernel<<<B_ROWS, THREADS, shmem>>>(outputs, targets, (float*)d_out);
}

// round 5
// speedup vs baseline: 4.6662x; 1.0790x over previous
#include <cuda_runtime.h>

#define B_ROWS 4096
#define N_LEN  8192
#define M_FFT  4096
#define THREADS 512

#define MIN_IDX 273           // argmin |f - 40/60|  (f[i] = i*5/2048, exact fp32)
#define MAX_IDX 1707          // argmin |f - 250/60|
#define DF 0.00244140625f     // 10/4096, exact fp32

#define TW_N 1025             // twiddles needed: p in [0, 1024]
#define TW_PAD 1032           // padded to float4 multiple

__device__ float g_losses[B_ROWS];
__device__ __align__(16) float2 g_tw[TW_PAD];   // exp(-2*pi*i*p/4096)
__device__ unsigned int g_ctr = 0;              // last-CTA counter (self-resetting)

// Build the twiddle table once per launch.
__global__ void twiddle_init_kernel()
{
    int p = blockIdx.x * blockDim.x + threadIdx.x;
    if (p < TW_PAD) {
        float s, c;
        sincospif(-(float)p * (1.0f / 2048.0f), &s, &c);  // -2*pi*p/4096
        g_tw[p] = make_float2(c, s);
    }
}

// GF(2)-linear swizzle on float2 indices. Designed so every access pattern
// below has 16 distinct (mod 16) indices within each 16-lane phase of a
// 64-bit shared access:
//   bit6 -> bit0, bit9 -> bit1, bit7^bit10 -> bit2, bit8^bit11 -> bit3.
__host__ __device__ constexpr int Sc(int i)
{
    return i ^ ((i >> 6) & 1) ^ ((i >> 5) & 0xC) ^ ((i >> 8) & 0xE);
}

__device__ __forceinline__ void cmul(float ar, float ai, float br, float bi,
                                     float& cr, float& ci)
{
    cr = ar * br - ai * bi;
    ci = ar * bi + ai * br;
}

// 8-point DFT (DIT), natural order, in-place on register arrays.
__device__ __forceinline__ void dft8(float* xr, float* xi)
{
    const float C = 0.70710678118654752f;
    float t0r = xr[0] + xr[4], t0i = xi[0] + xi[4];
    float t1r = xr[0] - xr[4], t1i = xi[0] - xi[4];
    float t2r = xr[2] + xr[6], t2i = xi[2] + xi[6];
    float t3r = xr[2] - xr[6], t3i = xi[2] - xi[6];
    float E0r = t0r + t2r, E0i = t0i + t2i;
    float E2r = t0r - t2r, E2i = t0i - t2i;
    float E1r = t1r + t3i, E1i = t1i - t3r;
    float E3r = t1r - t3i, E3i = t1i + t3r;
    float s0r = xr[1] + xr[5], s0i = xi[1] + xi[5];
    float s1r = xr[1] - xr[5], s1i = xi[1] - xi[5];
    float s2r = xr[3] + xr[7], s2i = xi[3] + xi[7];
    float s3r = xr[3] - xr[7], s3i = xi[3] - xi[7];
    float O0r = s0r + s2r, O0i = s0i + s2i;
    float O2r = s0r - s2r, O2i = s0i - s2i;
    float O1r = s1r + s3i, O1i = s1i - s3r;
    float O3r = s1r - s3i, O3i = s1i + s3r;
    float P1r = C * (O1r + O1i), P1i = C * (O1i - O1r);
    float P2r = O2i,             P2i = -O2r;
    float P3r = C * (O3i - O3r), P3i = -C * (O3r + O3i);
    xr[0] = E0r + O0r; xi[0] = E0i + O0i;
    xr[4] = E0r - O0r; xi[4] = E0i - O0i;
    xr[1] = E1r + P1r; xi[1] = E1i + P1i;
    xr[5] = E1r - P1r; xi[5] = E1i - P1i;
    xr[2] = E2r + P2r; xi[2] = E2i + P2i;
    xr[6] = E2r - P2r; xi[6] = E2i - P2i;
    xr[3] = E3r + P3r; xi[3] = E3i + P3i;
    xr[7] = E3r - P3r; xi[7] = E3i - P3i;
}

// One radix-8 DIT stage on AoS float2 data. Addresses: Sc(base) ^ Sc(k*L),
// Sc(k*L) folded at compile time.
template <int L>
__device__ __forceinline__ void stage(float2* z, const float2* tw, int tid)
{
    int p, g;
    if (L == 8)       { p = tid >> 6; g = tid & 63; }
    else if (L == 64) { p = tid >> 3; g = tid & 7;  }
    else              { p = tid;      g = 0;        }  // L == 512
    const int base = g * (8 * L) + p;
    const int q0   = Sc(base);
    const float2 w1 = tw[p * (512 / L)];

    float xr[8], xi[8];
    {
        float2 v = z[q0];
        xr[0] = v.x; xi[0] = v.y;
    }
    float wr = w1.x, wi = w1.y;
    #pragma unroll
    for (int k = 1; k < 8; ++k) {
        float2 v = z[q0 ^ Sc(k * L)];
        cmul(v.x, v.y, wr, wi, xr[k], xi[k]);
        if (k < 7) { float nr, ni; cmul(wr, wi, w1.x, w1.y, nr, ni); wr = nr; wi = ni; }
    }
    dft8(xr, xi);
    #pragma unroll
    for (int k = 0; k < 8; ++k)
        z[q0 ^ Sc(k * L)] = make_float2(xr[k], xi[k]);
}

__global__ void __launch_bounds__(THREADS, 3) snr_fft_kernel(
    const float* __restrict__ outputs,
    const float* __restrict__ targets,
    float* __restrict__ d_out)
{
    extern __shared__ float smem_raw[];
    float2* z  = reinterpret_cast<float2*>(smem_raw);          // 4096 float2 = 32KB
    float2* tw = z + M_FFT;                                    // 1032 float2 = 8.3KB

    const int tid = threadIdx.x;
    const int row = blockIdx.x;

    // Twiddle copy (gmem L2-resident -> smem), vectorized: 516 float4.
    {
        const float4* src = reinterpret_cast<const float4*>(g_tw);
        float4* dst = reinterpret_cast<float4*>(tw);
        dst[tid] = src[tid];
        if (tid < 4) dst[512 + tid] = src[512 + tid];
    }

    // Fused coalesced load + stage 1 (twiddle-free dft8 in registers).
    const float2* xrow = reinterpret_cast<const float2*>(outputs) + (size_t)row * M_FFT;
    {
        float xr[8], xi[8];
        #pragma unroll
        for (int k = 0; k < 8; ++k) {
            float2 v = xrow[tid + (k << 9)];
            xr[k] = v.x; xi[k] = v.y;
        }
        dft8(xr, xi);
        const int t8 = ((tid & 7) << 6) | (((tid >> 3) & 7) << 3) | (tid >> 6);
        const int q0 = Sc(t8 << 3);
        #pragma unroll
        for (int k = 0; k < 8; ++k)        // Sc(k) = k for k < 8
            z[q0 ^ k] = make_float2(xr[k], xi[k]);
    }
    __syncthreads();

    stage<8>(z, tw, tid);
    __syncthreads();
    stage<64>(z, tw, tid);
    __syncthreads();
    stage<512>(z, tw, tid);
    __syncthreads();

    // r = argmin_i |f[i] - target| (first-min tie rule)
    const float tgt = targets[row];
    int base = (int)floorf(tgt / DF) - 1;
    if (base < 0) base = 0;
    if (base > M_FFT - 3) base = M_FFT - 3;
    int r = base;
    float best = fabsf((float)base * DF - tgt);
    #pragma unroll
    for (int i = 1; i <= 3; ++i) {
        float d = fabsf((float)(base + i) * DF - tgt);
        if (d < best) { best = d; r = base + i; }
    }
    const int r2 = 2 * r;

    // exp(-i*pi/4096) for odd-k unpack twiddles
    const float Cr = 0.99999970586288222f;
    const float Ci = -0.00076699031874270449f;

    // Paired epilogue: k in [272, 2048]; bins b=k and b=4096-k share
    // (Z[k], Z[4096-k]); W[4096-k] = -conj(W[k]).
    float sig = 0.0f, noi = 0.0f;
    for (int k = 272 + tid; k <= 2048; k += THREADS) {
        float2 Z1 = z[Sc(k)];
        float2 Z2 = z[Sc(M_FFT - k)];
        float Er = 0.5f * (Z1.x + Z2.x);
        float Ei = 0.5f * (Z1.y - Z2.y);
        float Or = 0.5f * (Z1.y + Z2.y);
        float Oi = 0.5f * (Z2.x - Z1.x);
        float2 W = tw[k >> 1];
        float Wr = W.x, Wi = W.y;
        if (k & 1) { float nr, ni; cmul(Wr, Wi, Cr, Ci, nr, ni); Wr = nr; Wi = ni; }

        // Bin k
        {
            float Xr = Er + Wr * Or - Wi * Oi;
            float Xi = Ei + Wr * Oi + Wi * Or;
            float pwr = (Xr * Xr + Xi * Xi) * (1.0f / (float)N_LEN);
            float u = (k == r || k == r2) ? 1.0f
                    : ((k == r - 1 || k == r + 1) ? 0.5f : 0.0f);
            bool inr = (k >= MIN_IDX) && (k < MAX_IDX);
            float w = (!inr || k == r2 - 1 || k == r2 + 1) ? 0.0f : (1.0f - u);
            sig += pwr * u;
            noi += pwr * w;
        }

        // Bin m = 4096 - k (noise weight is 0 there; only u can hit).
        int m = M_FFT - k;
        if (k >= 681 && k < 2048) {
            float Xr = Er - Wr * Or - Wi * Oi;
            float Xi = -Ei - Wr * Oi + Wi * Or;
            float pwr = (Xr * Xr + Xi * Xi) * (1.0f / (float)N_LEN);
            float u = (m == r || m == r2) ? 1.0f
                    : ((m == r - 1 || m == r + 1) ? 0.5f : 0.0f);
            sig += pwr * u;
        }
    }

    #pragma unroll
    for (int o = 16; o > 0; o >>= 1) {
        sig += __shfl_down_sync(0xffffffffu, sig, o);
        noi += __shfl_down_sync(0xffffffffu, noi, o);
    }
    const int wid = tid >> 5, lane = tid & 31;
    float* red = reinterpret_cast<float*>(tw);   // smem reads of tw done
    __syncthreads();
    if (lane == 0) { red[wid] = sig; red[16 + wid] = noi; }
    __syncthreads();

    __shared__ bool is_last;
    if (tid == 0) {
        float Sg = 0.0f, Nq = 0.0f;
        #pragma unroll
        for (int i = 0; i < 16; ++i) { Sg += red[i]; Nq += red[16 + i]; }
        g_losses[row] = -10.0f * log10f(Sg / (Nq + 1.0f));
        __threadfence();
        unsigned int old = atomicAdd(&g_ctr, 1u);
        is_last = (old == (unsigned int)(B_ROWS - 1));
    }
    __syncthreads();

    // Last CTA computes the mean (fixed-order, deterministic), resets ctr.
    if (is_last) {
        float s = 0.0f;
        for (int i = tid; i < B_ROWS; i += THREADS) s += g_losses[i];
        #pragma unroll
        for (int o = 16; o > 0; o >>= 1) s += __shfl_down_sync(0xffffffffu, s, o);
        __syncthreads();
        if (lane == 0) red[wid] = s;
        __syncthreads();
        if (tid == 0) {
            float t = 0.0f;
            #pragma unroll
            for (int i = 0; i < 16; ++i) t += red[i];
            d_out[0] = t * (1.0f / (float)B_ROWS);
            g_ctr = 0;
        }
    }
}

extern "C" void kernel_launch(void* const* d_in, const int* in_sizes, int n_in,
                              void* d_out, int out_size)
{
    const float* outputs = (const float*)d_in[0];   // [4096, 8192] f32
    const float* targets = (const float*)d_in[1];   // [4096, 1]    f32
    (void)in_sizes; (void)n_in; (void)out_size;

    const size_t shmem = sizeof(float2) * (M_FFT + TW_PAD);   // 41024 B
    cudaFuncSetAttribute(snr_fft_kernel,
                         cudaFuncAttributeMaxDynamicSharedMemorySize, 65536);

    twiddle_init_kernel<<<3, 512>>>();
    snr_fft_kernel<<<B_ROWS, THREADS, shmem>>>(outputs, targets, (float*)d_out);
}

// round 6
// speedup vs baseline: 5.2656x; 1.1285x over previous
#include <cuda_runtime.h>

#define B_ROWS 4096
#define N_LEN  8192
#define M_FFT  4096
#define THREADS 512

#define MIN_IDX 273           // argmin |f - 40/60|  (f[i] = i*5/2048, exact fp32)
#define MAX_IDX 1707          // argmin |f - 250/60|  (band = [273, 1707) )
#define DF 0.00244140625f     // 10/4096, exact fp32

#define TW_N 3416             // T[p] = exp(-i*pi*p/4096), p in [0, 3415]
#define TW_PAD 3420           // even (float4-aligned float2 count)

__device__ float g_losses[B_ROWS];
__device__ __align__(16) float2 g_tw[TW_PAD];
__device__ unsigned int g_ctr = 0;              // last-CTA counter (self-resetting)

// Build half-angle twiddle table once per launch: T[p] = exp(-i*pi*p/4096).
__global__ void twiddle_init_kernel()
{
    int p = blockIdx.x * blockDim.x + threadIdx.x;
    if (p < TW_PAD) {
        float s, c;
        sincospif(-(float)p * (1.0f / 4096.0f), &s, &c);
        g_tw[p] = make_float2(c, s);
    }
}

// GF(2)-linear swizzle on float2 indices (conflict-free for all stage
// patterns; verified in R5, rel_err unchanged).
__host__ __device__ constexpr int Sc(int i)
{
    return i ^ ((i >> 6) & 1) ^ ((i >> 5) & 0xC) ^ ((i >> 8) & 0xE);
}

__device__ __forceinline__ void cmul(float ar, float ai, float br, float bi,
                                     float& cr, float& ci)
{
    cr = ar * br - ai * bi;
    ci = ar * bi + ai * br;
}

// 8-point DFT (DIT), natural order, in-place on register arrays.
__device__ __forceinline__ void dft8(float* xr, float* xi)
{
    const float C = 0.70710678118654752f;
    float t0r = xr[0] + xr[4], t0i = xi[0] + xi[4];
    float t1r = xr[0] - xr[4], t1i = xi[0] - xi[4];
    float t2r = xr[2] + xr[6], t2i = xi[2] + xi[6];
    float t3r = xr[2] - xr[6], t3i = xi[2] - xi[6];
    float E0r = t0r + t2r, E0i = t0i + t2i;
    float E2r = t0r - t2r, E2i = t0i - t2i;
    float E1r = t1r + t3i, E1i = t1i - t3r;
    float E3r = t1r - t3i, E3i = t1i + t3r;
    float s0r = xr[1] + xr[5], s0i = xi[1] + xi[5];
    float s1r = xr[1] - xr[5], s1i = xi[1] - xi[5];
    float s2r = xr[3] + xr[7], s2i = xi[3] + xi[7];
    float s3r = xr[3] - xr[7], s3i = xi[3] - xi[7];
    float O0r = s0r + s2r, O0i = s0i + s2i;
    float O2r = s0r - s2r, O2i = s0i - s2i;
    float O1r = s1r + s3i, O1i = s1i - s3r;
    float O3r = s1r - s3i, O3i = s1i + s3r;
    float P1r = C * (O1r + O1i), P1i = C * (O1i - O1r);
    float P2r = O2i,             P2i = -O2r;
    float P3r = C * (O3i - O3r), P3i = -C * (O3r + O3i);
    xr[0] = E0r + O0r; xi[0] = E0i + O0i;
    xr[4] = E0r - O0r; xi[4] = E0i - O0i;
    xr[1] = E1r + P1r; xi[1] = E1i + P1i;
    xr[5] = E1r - P1r; xi[5] = E1i - P1i;
    xr[2] = E2r + P2r; xi[2] = E2i + P2i;
    xr[6] = E2r - P2r; xi[6] = E2i - P2i;
    xr[3] = E3r + P3r; xi[3] = E3i + P3i;
    xr[7] = E3r - P3r; xi[7] = E3i - P3i;
}

// One radix-8 DIT stage on AoS float2 data. Twiddle base from the half-angle
// table: w1 = T[2*tix] = exp(-2*pi*i*tix/4096).
template <int L>
__device__ __forceinline__ void stage(float2* z, const float2* T, int tid)
{
    int p, g;
    if (L == 8)       { p = tid >> 6; g = tid & 63; }
    else              { p = tid >> 3; g = tid & 7;  }   // L == 64
    const int base = g * (8 * L) + p;
    const int q0   = Sc(base);
    const float2 w1 = T[p * (1024 / L)];

    float xr[8], xi[8];
    {
        float2 v = z[q0];
        xr[0] = v.x; xi[0] = v.y;
    }
    float wr = w1.x, wi = w1.y;
    #pragma unroll
    for (int k = 1; k < 8; ++k) {
        float2 v = z[q0 ^ Sc(k * L)];
        cmul(v.x, v.y, wr, wi, xr[k], xi[k]);
        if (k < 7) { float nr, ni; cmul(wr, wi, w1.x, w1.y, nr, ni); wr = nr; wi = ni; }
    }
    dft8(xr, xi);
    #pragma unroll
    for (int k = 0; k < 8; ++k)
        z[q0 ^ Sc(k * L)] = make_float2(xr[k], xi[k]);
}

__global__ void __launch_bounds__(THREADS, 3) snr_fft_kernel(
    const float* __restrict__ outputs,
    const float* __restrict__ targets,
    float* __restrict__ d_out)
{
    extern __shared__ float smem_raw[];
    float2* z = reinterpret_cast<float2*>(smem_raw);   // 4096 float2 = 32KB
    float2* T = z + M_FFT;                             // 3420 float2 = 27.4KB

    const int tid = threadIdx.x;
    const int row = blockIdx.x;

    // Twiddle copy (gmem L2-resident -> smem): 1710 float4.
    {
        const float4* src = reinterpret_cast<const float4*>(g_tw);
        float4* dst = reinterpret_cast<float4*>(T);
        #pragma unroll
        for (int i = tid; i < TW_PAD / 2; i += THREADS) dst[i] = src[i];
    }

    // Fused coalesced load + stage 1 (twiddle-free dft8 in registers).
    const float2* xrow = reinterpret_cast<const float2*>(outputs) + (size_t)row * M_FFT;
    {
        float xr[8], xi[8];
        #pragma unroll
        for (int k = 0; k < 8; ++k) {
            float2 v = xrow[tid + (k << 9)];
            xr[k] = v.x; xi[k] = v.y;
        }
        dft8(xr, xi);
        const int t8 = ((tid & 7) << 6) | (((tid >> 3) & 7) << 3) | (tid >> 6);
        const int q0 = Sc(t8 << 3);
        #pragma unroll
        for (int k = 0; k < 8; ++k)        // Sc(k) = k for k < 8
            z[q0 ^ k] = make_float2(xr[k], xi[k]);
    }
    __syncthreads();

    stage<8>(z, T, tid);
    __syncthreads();
    stage<64>(z, T, tid);
    __syncthreads();

    // Stage L=512 inlined; final Z[tid + 512c] kept in registers.
    float xr[8], xi[8];
    {
        const int q0 = Sc(tid);
        const float2 w1 = T[2 * tid];
        {
            float2 v = z[q0];
            xr[0] = v.x; xi[0] = v.y;
        }
        float wr = w1.x, wi = w1.y;
        #pragma unroll
        for (int k = 1; k < 8; ++k) {
            float2 v = z[q0 ^ Sc(k * 512)];
            cmul(v.x, v.y, wr, wi, xr[k], xi[k]);
            if (k < 7) { float nr, ni; cmul(wr, wi, w1.x, w1.y, nr, ni); wr = nr; wi = ni; }
        }
        dft8(xr, xi);
    }
    __syncthreads();   // everyone done READING stages' data
    {
        const int q0 = Sc(tid);
        #pragma unroll
        for (int k = 0; k < 8; ++k)
            z[q0 ^ Sc(k * 512)] = make_float2(xr[k], xi[k]);
    }
    __syncthreads();   // final Z fully published

    // r = argmin_i |f[i] - target| (first-min tie rule)
    const float tgt = targets[row];
    int ib = (int)floorf(tgt / DF) - 1;
    if (ib < 0) ib = 0;
    if (ib > M_FFT - 3) ib = M_FFT - 3;
    int r = ib;
    float best = fabsf((float)ib * DF - tgt);
    #pragma unroll
    for (int i = 1; i <= 3; ++i) {
        float d = fabsf((float)(ib + i) * DF - tgt);
        if (d < best) { best = d; r = ib + i; }
    }

    // Weight-free band sum over k in [273, 1706]; Z1 from registers.
    float band = 0.0f;
    #pragma unroll
    for (int c = 0; c < 4; ++c) {
        int k = tid + (c << 9);
        bool valid = (c == 1) || (c == 2) ||
                     (c == 0 ? (tid >= MIN_IDX) : (k <= MAX_IDX - 1));
        if (valid) {
            float2 Z2 = z[Sc(M_FFT - k)];
            float Er = 0.5f * (xr[c] + Z2.x);
            float Ei = 0.5f * (xi[c] - Z2.y);
            float Or = 0.5f * (xi[c] + Z2.y);
            float Oi = 0.5f * (Z2.x - xr[c]);
            float2 W = T[k];
            float Xr = Er + W.x * Or - W.y * Oi;
            float Xi = Ei + W.x * Oi + W.y * Or;
            band += (Xr * Xr + Xi * Xi) * (1.0f / (float)N_LEN);
        }
    }

    // Special bins: {r-1, r, r+1, 2r-1, 2r, 2r+1}, threads 0..5.
    float spec_sig = 0.0f, spec_corr = 0.0f;
    if (tid < 6) {
        const int   joff[6] = { -1, 0, 1, -1, 0, 1 };
        const float uw[6]   = { 0.5f, 1.0f, 0.5f, 0.0f, 1.0f, 0.0f };
        const float mw[6]   = { 0.5f, 1.0f, 0.5f, 1.0f, 1.0f, 1.0f };
        int j = (tid < 3 ? r : 2 * r) + joff[tid];
        float2 Z1 = z[Sc(j)];
        float2 Z2 = z[Sc(M_FFT - j)];
        float Er = 0.5f * (Z1.x + Z2.x);
        float Ei = 0.5f * (Z1.y - Z2.y);
        float Or = 0.5f * (Z1.y + Z2.y);
        float Oi = 0.5f * (Z2.x - Z1.x);
        float2 W = T[j];
        float Xr = Er + W.x * Or - W.y * Oi;
        float Xi = Ei + W.x * Oi + W.y * Or;
        float P = (Xr * Xr + Xi * Xi) * (1.0f / (float)N_LEN);
        spec_sig  = uw[tid] * P;
        spec_corr = (j >= MIN_IDX && j < MAX_IDX) ? mw[tid] * P : 0.0f;
    }

    // Reductions.
    #pragma unroll
    for (int o = 16; o > 0; o >>= 1)
        band += __shfl_down_sync(0xffffffffu, band, o);
    #pragma unroll
    for (int o = 4; o > 0; o >>= 1) {     // lanes 0..5 live in warp 0
        spec_sig  += __shfl_down_sync(0xffffffffu, spec_sig,  o);
        spec_corr += __shfl_down_sync(0xffffffffu, spec_corr, o);
    }
    const int wid = tid >> 5, lane = tid & 31;
    float* red = reinterpret_cast<float*>(T);   // T smem reads are done
    __syncthreads();
    if (lane == 0) red[wid] = band;
    if (tid == 0) { red[16] = spec_sig; red[17] = spec_corr; }
    __syncthreads();

    __shared__ bool is_last;
    if (tid == 0) {
        float Bt = 0.0f;
        #pragma unroll
        for (int i = 0; i < 16; ++i) Bt += red[i];
        float Sg = red[16];
        float Nq = Bt - red[17];
        g_losses[row] = -10.0f * log10f(Sg / (Nq + 1.0f));
        __threadfence();
        unsigned int old = atomicAdd(&g_ctr, 1u);
        is_last = (old == (unsigned int)(B_ROWS - 1));
    }
    __syncthreads();

    // Last CTA computes the mean (fixed-order, deterministic), resets ctr.
    if (is_last) {
        float s = 0.0f;
        for (int i = tid; i < B_ROWS; i += THREADS) s += g_losses[i];
        #pragma unroll
        for (int o = 16; o > 0; o >>= 1) s += __shfl_down_sync(0xffffffffu, s, o);
        __syncthreads();
        if (lane == 0) red[wid] = s;
        __syncthreads();
        if (tid == 0) {
            float t = 0.0f;
            #pragma unroll
            for (int i = 0; i < 16; ++i) t += red[i];
            d_out[0] = t * (1.0f / (float)B_ROWS);
            g_ctr = 0;
        }
    }
}

extern "C" void kernel_launch(void* const* d_in, const int* in_sizes, int n_in,
                              void* d_out, int out_size)
{
    const float* outputs = (const float*)d_in[0];   // [4096, 8192] f32
    const float* targets = (const float*)d_in[1];   // [4096, 1]    f32
    (void)in_sizes; (void)n_in; (void)out_size;

    const size_t shmem = sizeof(float2) * (M_FFT + TW_PAD);   // 60128 B
    cudaFuncSetAttribute(snr_fft_kernel,
                         cudaFuncAttributeMaxDynamicSharedMemorySize, 65536);

    twiddle_init_kernel<<<7, 512>>>();
    snr_fft_kernel<<<B_ROWS, THREADS, shmem>>>(outputs, targets, (float*)d_out);
}

// round 7
// speedup vs baseline: 5.4670x; 1.0382x over previous
#include <cuda_runtime.h>
#include <cstdint>

#define B_ROWS 4096
#define N_LEN  8192
#define M_FFT  4096
#define THREADS 512

#define MIN_IDX 273           // argmin |f - 40/60|  (f[i] = i*5/2048, exact fp32)
#define MAX_IDX 1707          // argmin |f - 250/60|  (band = [273, 1707) )
#define DF 0.00244140625f     // 10/4096, exact fp32

#define TW_N   2049           // T[p] = exp(-i*pi*p/4096), p in [0, 2048]
#define TW_PAD 2052           // float4-aligned count
#define TW_BYTES (TW_PAD * 8) // 16416, multiple of 16

// smem layout (bytes from dynamic base)
#define Z_OFF    0
#define T_OFF    32768
#define MBAR_OFF (T_OFF + TW_BYTES)     // 49184
#define SMEM_TOTAL (MBAR_OFF + 16)      // 49200

__device__ float g_losses[B_ROWS];
__device__ __align__(16) float2 g_tw[TW_PAD];
__device__ unsigned int g_ctr = 0;      // last-CTA counter (self-resetting)

__global__ void twiddle_init_kernel()
{
    int p = blockIdx.x * blockDim.x + threadIdx.x;
    if (p < TW_PAD) {
        float s, c;
        sincospif(-(float)p * (1.0f / 4096.0f), &s, &c);
        g_tw[p] = make_float2(c, s);
    }
}

__device__ __forceinline__ uint32_t smem_u32(const void* p)
{
    uint32_t a;
    asm("{ .reg .u64 t; cvta.to.shared.u64 t, %1; cvt.u32.u64 %0, t; }"
        : "=r"(a) : "l"(p));
    return a;
}

// GF(2)-linear swizzle on float2 indices (conflict-free for all stage
// patterns; validated R5/R6, rel_err 0).
__host__ __device__ constexpr int Sc(int i)
{
    return i ^ ((i >> 6) & 1) ^ ((i >> 5) & 0xC) ^ ((i >> 8) & 0xE);
}

__device__ __forceinline__ void cmul(float ar, float ai, float br, float bi,
                                     float& cr, float& ci)
{
    cr = ar * br - ai * bi;
    ci = ar * bi + ai * br;
}

// 8-point DFT (DIT), natural order, in-place on register arrays.
__device__ __forceinline__ void dft8(float* xr, float* xi)
{
    const float C = 0.70710678118654752f;
    float t0r = xr[0] + xr[4], t0i = xi[0] + xi[4];
    float t1r = xr[0] - xr[4], t1i = xi[0] - xi[4];
    float t2r = xr[2] + xr[6], t2i = xi[2] + xi[6];
    float t3r = xr[2] - xr[6], t3i = xi[2] - xi[6];
    float E0r = t0r + t2r, E0i = t0i + t2i;
    float E2r = t0r - t2r, E2i = t0i - t2i;
    float E1r = t1r + t3i, E1i = t1i - t3r;
    float E3r = t1r - t3i, E3i = t1i + t3r;
    float s0r = xr[1] + xr[5], s0i = xi[1] + xi[5];
    float s1r = xr[1] - xr[5], s1i = xi[1] - xi[5];
    float s2r = xr[3] + xr[7], s2i = xi[3] + xi[7];
    float s3r = xr[3] - xr[7], s3i = xi[3] - xi[7];
    float O0r = s0r + s2r, O0i = s0i + s2i;
    float O2r = s0r - s2r, O2i = s0i - s2i;
    float O1r = s1r + s3i, O1i = s1i - s3r;
    float O3r = s1r - s3i, O3i = s1i + s3r;
    float P1r = C * (O1r + O1i), P1i = C * (O1i - O1r);
    float P2r = O2i,             P2i = -O2r;
    float P3r = C * (O3i - O3r), P3i = -C * (O3r + O3i);
    xr[0] = E0r + O0r; xi[0] = E0i + O0i;
    xr[4] = E0r - O0r; xi[4] = E0i - O0i;
    xr[1] = E1r + P1r; xi[1] = E1i + P1i;
    xr[5] = E1r - P1r; xi[5] = E1i - P1i;
    xr[2] = E2r + P2r; xi[2] = E2i + P2i;
    xr[6] = E2r - P2r; xi[6] = E2i - P2i;
    xr[3] = E3r + P3r; xi[3] = E3i + P3i;
    xr[7] = E3r - P3r; xi[7] = E3i - P3i;
}

// Twiddle powers w^1..w^7 via depth-3 tree.
__device__ __forceinline__ void wpowers(float w1r, float w1i, float* wr, float* wi)
{
    wr[1] = w1r; wi[1] = w1i;
    cmul(w1r, w1i, w1r, w1i, wr[2], wi[2]);
    cmul(wr[2], wi[2], w1r, w1i, wr[3], wi[3]);
    cmul(wr[2], wi[2], wr[2], wi[2], wr[4], wi[4]);
    cmul(wr[2], wi[2], wr[3], wi[3], wr[5], wi[5]);
    cmul(wr[3], wi[3], wr[3], wi[3], wr[6], wi[6]);
    cmul(wr[3], wi[3], wr[4], wi[4], wr[7], wi[7]);
}

// One radix-8 DIT stage on AoS float2 data; butterflies partition the array
// per-thread, so no sync needed between its reads and writes.
template <int L>
__device__ __forceinline__ void stage(float2* z, const float2* T, int tid)
{
    int p, g;
    if (L == 8)       { p = tid >> 6; g = tid & 63; }
    else              { p = tid >> 3; g = tid & 7;  }   // L == 64
    const int base = g * (8 * L) + p;
    const int q0   = Sc(base);
    const float2 w1 = T[p * (1024 / L)];   // exp(-2*pi*i*p/(8L))

    float wr[8], wi[8];
    wpowers(w1.x, w1.y, wr, wi);

    float xr[8], xi[8];
    {
        float2 v = z[q0];
        xr[0] = v.x; xi[0] = v.y;
    }
    #pragma unroll
    for (int k = 1; k < 8; ++k) {
        float2 v = z[q0 ^ Sc(k * L)];
        cmul(v.x, v.y, wr[k], wi[k], xr[k], xi[k]);
    }
    dft8(xr, xi);
    #pragma unroll
    for (int k = 0; k < 8; ++k)
        z[q0 ^ Sc(k * L)] = make_float2(xr[k], xi[k]);
}

__global__ void __launch_bounds__(THREADS, 3) snr_fft_kernel(
    const float* __restrict__ outputs,
    const float* __restrict__ targets,
    float* __restrict__ d_out)
{
    extern __shared__ float smem_raw[];
    char* sb = reinterpret_cast<char*>(smem_raw);
    float2* z = reinterpret_cast<float2*>(sb + Z_OFF);   // 4096 float2
    float2* T = reinterpret_cast<float2*>(sb + T_OFF);   // 2052 float2

    const int tid = threadIdx.x;
    const int row = blockIdx.x;
    const uint32_t mbar = smem_u32(sb + MBAR_OFF);

    // Async bulk copy of the twiddle table (overlaps with loads + stage 1).
    if (tid == 0) {
        asm volatile("mbarrier.init.shared.b64 [%0], 1;" :: "r"(mbar) : "memory");
        asm volatile("mbarrier.arrive.expect_tx.shared.b64 _, [%0], %1;"
                     :: "r"(mbar), "r"((uint32_t)TW_BYTES) : "memory");
        asm volatile("cp.async.bulk.shared::cluster.global.mbarrier::complete_tx::bytes "
                     "[%0], [%1], %2, [%3];"
                     :: "r"(smem_u32(T)), "l"((const void*)g_tw),
                        "r"((uint32_t)TW_BYTES), "r"(mbar) : "memory");
    }

    // Fused coalesced load + stage 1 (twiddle-free dft8 in registers).
    const float2* xrow = reinterpret_cast<const float2*>(outputs) + (size_t)row * M_FFT;
    {
        float xr[8], xi[8];
        #pragma unroll
        for (int k = 0; k < 8; ++k) {
            float2 v = xrow[tid + (k << 9)];
            xr[k] = v.x; xi[k] = v.y;
        }
        dft8(xr, xi);
        const int t8 = ((tid & 7) << 6) | (((tid >> 3) & 7) << 3) | (tid >> 6);
        const int q0 = Sc(t8 << 3);
        #pragma unroll
        for (int k = 0; k < 8; ++k)        // Sc(k) = k for k < 8
            z[q0 ^ k] = make_float2(xr[k], xi[k]);
    }
    __syncthreads();     // stage-1 data published; also orders mbar init

    // Wait for the twiddle table before first T use.
    asm volatile(
        "{\n\t.reg .pred P;\n"
        "WAITL%=:\n\t"
        "mbarrier.try_wait.parity.acquire.cta.shared::cta.b64 P, [%0], 0;\n\t"
        "@!P bra WAITL%=;\n\t}"
        :: "r"(mbar) : "memory");

    stage<8>(z, T, tid);
    __syncthreads();
    stage<64>(z, T, tid);
    __syncthreads();

    // Stage L=512 inlined; final Z[tid + 512c] kept in registers.
    // Per-thread partitioned read/write set -> no barrier inside the stage.
    float xr[8], xi[8];
    {
        const int q0 = Sc(tid);
        const float2 w1 = T[2 * tid];
        float wr[8], wi[8];
        wpowers(w1.x, w1.y, wr, wi);
        {
            float2 v = z[q0];
            xr[0] = v.x; xi[0] = v.y;
        }
        #pragma unroll
        for (int k = 1; k < 8; ++k) {
            float2 v = z[q0 ^ Sc(k * 512)];
            cmul(v.x, v.y, wr[k], wi[k], xr[k], xi[k]);
        }
        dft8(xr, xi);
        #pragma unroll
        for (int k = 0; k < 8; ++k)
            z[q0 ^ Sc(k * 512)] = make_float2(xr[k], xi[k]);
    }
    __syncthreads();     // final Z fully published

    // r = argmin_i |f[i] - target| (first-min tie rule)
    const float tgt = targets[row];
    int ib = (int)floorf(tgt / DF) - 1;
    if (ib < 0) ib = 0;
    if (ib > M_FFT - 3) ib = M_FFT - 3;
    int r = ib;
    float best = fabsf((float)ib * DF - tgt);
    #pragma unroll
    for (int i = 1; i <= 3; ++i) {
        float d = fabsf((float)(ib + i) * DF - tgt);
        if (d < best) { best = d; r = ib + i; }
    }

    // Weight-free band sum over k in [273, 1706]; Z1 from registers.
    float band = 0.0f;
    #pragma unroll
    for (int c = 0; c < 4; ++c) {
        int k = tid + (c << 9);
        bool valid = (c == 1) || (c == 2) ||
                     (c == 0 ? (tid >= MIN_IDX) : (k <= MAX_IDX - 1));
        if (valid) {
            float2 Z2 = z[Sc(M_FFT - k)];
            float Er = 0.5f * (xr[c] + Z2.x);
            float Ei = 0.5f * (xi[c] - Z2.y);
            float Or = 0.5f * (xi[c] + Z2.y);
            float Oi = 0.5f * (Z2.x - xr[c]);
            float2 W = T[k];            // k <= 1706 < TW_N
            float Xr = Er + W.x * Or - W.y * Oi;
            float Xi = Ei + W.x * Oi + W.y * Or;
            band += (Xr * Xr + Xi * Xi) * (1.0f / (float)N_LEN);
        }
    }

    // Special bins: {r-1, r, r+1, 2r-1, 2r, 2r+1}, threads 0..5.
    float spec_sig = 0.0f, spec_corr = 0.0f;
    if (tid < 6) {
        const int   joff[6] = { -1, 0, 1, -1, 0, 1 };
        const float uw[6]   = { 0.5f, 1.0f, 0.5f, 0.0f, 1.0f, 0.0f };
        const float mw[6]   = { 0.5f, 1.0f, 0.5f, 1.0f, 1.0f, 1.0f };
        int j = (tid < 3 ? r : 2 * r) + joff[tid];
        float2 Z1 = z[Sc(j)];
        float2 Z2 = z[Sc(M_FFT - j)];
        float Er = 0.5f * (Z1.x + Z2.x);
        float Ei = 0.5f * (Z1.y - Z2.y);
        float Or = 0.5f * (Z1.y + Z2.y);
        float Oi = 0.5f * (Z2.x - Z1.x);
        float2 W;
        if (j <= 2048) {
            W = T[j];
        } else {                         // T[j] = -conj(T[4096-j])
            float2 Wm = T[M_FFT - j];
            W = make_float2(-Wm.x, Wm.y);
        }
        float Xr = Er + W.x * Or - W.y * Oi;
        float Xi = Ei + W.x * Oi + W.y * Or;
        float P = (Xr * Xr + Xi * Xi) * (1.0f / (float)N_LEN);
        spec_sig  = uw[tid] * P;
        spec_corr = (j >= MIN_IDX && j < MAX_IDX) ? mw[tid] * P : 0.0f;
    }

    // Reductions.
    #pragma unroll
    for (int o = 16; o > 0; o >>= 1)
        band += __shfl_down_sync(0xffffffffu, band, o);
    #pragma unroll
    for (int o = 4; o > 0; o >>= 1) {     // lanes 0..5 live in warp 0
        spec_sig  += __shfl_down_sync(0xffffffffu, spec_sig,  o);
        spec_corr += __shfl_down_sync(0xffffffffu, spec_corr, o);
    }
    const int wid = tid >> 5, lane = tid & 31;
    float* red = reinterpret_cast<float*>(T);   // T reads are done
    __syncthreads();
    if (lane == 0) red[wid] = band;
    if (tid == 0) { red[16] = spec_sig; red[17] = spec_corr; }
    __syncthreads();

    __shared__ bool is_last;
    if (tid == 0) {
        float Bt = 0.0f;
        #pragma unroll
        for (int i = 0; i < 16; ++i) Bt += red[i];
        float Sg = red[16];
        float Nq = Bt - red[17];
        g_losses[row] = -10.0f * log10f(Sg / (Nq + 1.0f));
        __threadfence();
        unsigned int old = atomicAdd(&g_ctr, 1u);
        is_last = (old == (unsigned int)(B_ROWS - 1));
    }
    __syncthreads();

    // Last CTA computes the mean (fixed-order, deterministic), resets ctr.
    if (is_last) {
        float s = 0.0f;
        for (int i = tid; i < B_ROWS; i += THREADS) s += g_losses[i];
        #pragma unroll
        for (int o = 16; o > 0; o >>= 1) s += __shfl_down_sync(0xffffffffu, s, o);
        __syncthreads();
        if (lane == 0) red[wid] = s;
        __syncthreads();
        if (tid == 0) {
            float t = 0.0f;
            #pragma unroll
            for (int i = 0; i < 16; ++i) t += red[i];
            d_out[0] = t * (1.0f / (float)B_ROWS);
            g_ctr = 0;
        }
    }
}

extern "C" void kernel_launch(void* const* d_in, const int* in_sizes, int n_in,
                              void* d_out, int out_size)
{
    const float* outputs = (const float*)d_in[0];   // [4096, 8192] f32
    const float* targets = (const float*)d_in[1];   // [4096, 1]    f32
    (void)in_sizes; (void)n_in; (void)out_size;

    cudaFuncSetAttribute(snr_fft_kernel,
                         cudaFuncAttributeMaxDynamicSharedMemorySize, 65536);

    twiddle_init_kernel<<<5, 512>>>();
    snr_fft_kernel<<<B_ROWS, THREADS, SMEM_TOTAL>>>(outputs, targets, (float*)d_out);
}